// round 12
// baseline (speedup 1.0000x reference)
#include <cuda_runtime.h>
#include <cuda_fp16.h>
#include <cstdint>

#define B_TOK 32768
#define D_DIM 256
#define H_DIM 8192
#define K_TOP 32
#define CAP   384

// ---------------- static scratch (no cudaMalloc allowed) ----------------
__device__ __align__(256) __half g_xh[(size_t)B_TOK * D_DIM];                // 16 MB
__device__ __align__(256) __half g_wh[(size_t)H_DIM * D_DIM];                //  4 MB
__device__ __align__(16) unsigned long long g_cand[(size_t)B_TOK * CAP];     // 100 MB
__device__ int   g_cnt[B_TOK];
__device__ float g_tau[B_TOK];

// ---------------- K01: per-token threshold + counter zero ----------------
__global__ void tau_kernel(const float* __restrict__ x) {
    const int wid  = threadIdx.x >> 5;
    const int lane = threadIdx.x & 31;
    const int b    = blockIdx.x * 8 + wid;
    if (b >= B_TOK) return;
    const float4* xp = (const float4*)(x + (size_t)b * D_DIM);
    float4 u0 = xp[lane], u1 = xp[lane + 32];
    float s = u0.x*u0.x + u0.y*u0.y + u0.z*u0.z + u0.w*u0.w
            + u1.x*u1.x + u1.y*u1.y + u1.z*u1.z + u1.w*u1.w;
    #pragma unroll
    for (int o = 16; o; o >>= 1) s += __shfl_xor_sync(0xffffffffu, s, o);
    if (lane == 0) {
        g_tau[b] = 0.0430f * sqrtf(s);   // 2.15 * 0.02 * ||x||
        g_cnt[b] = 0;
    }
}

// ---------------- K0: fp32 -> fp16 conversion ----------------
__global__ void cvt_kernel(const float* __restrict__ x, const float* __restrict__ w) {
    const long long n1 = (long long)B_TOK * D_DIM / 4;
    const long long n2 = (long long)H_DIM * D_DIM / 4;
    long long i = blockIdx.x * (long long)blockDim.x + threadIdx.x;
    if (i < n1) {
        float4 v = ((const float4*)x)[i];
        __half2* o = (__half2*)g_xh;
        o[2 * i]     = __floats2half2_rn(v.x, v.y);
        o[2 * i + 1] = __floats2half2_rn(v.z, v.w);
    } else if (i < n1 + n2) {
        long long j = i - n1;
        float4 v = ((const float4*)w)[j];
        __half2* o = (__half2*)g_wh;
        o[2 * j]     = __floats2half2_rn(v.x, v.y);
        o[2 * j + 1] = __floats2half2_rn(v.z, v.w);
    }
}

// ================= K1: fp16 HMMA GEMM, 1024 threads (32 warps), tile 128x256 =================
#define BM 128
#define BN 256
#define BK 32
#define APITCH 40                          // f16 elems per smem row (32 + 8 pad); 80B rows
#define A_ELEMS (BM * APITCH)              // 5120 halfs  = 10240 B per buffer
#define B_ELEMS (BN * APITCH)              // 10240 halfs = 20480 B per buffer
#define GEMM_SMEM ((2 * A_ELEMS + 2 * B_ELEMS) * 2)   // 61440 bytes

__global__ void __launch_bounds__(1024, 1) enc_gemm_kernel(const float* __restrict__ b_enc) {
    extern __shared__ __align__(16) __half dynsmem[];
    __half* sA = dynsmem;                   // [2][A_ELEMS]
    __half* sB = dynsmem + 2 * A_ELEMS;     // [2][B_ELEMS]

    const int tid  = threadIdx.x;
    const int bm   = blockIdx.y, bn = blockIdx.x;
    const int wid  = tid >> 5,  lane = tid & 31;
    const int wm   = wid >> 3,  wn = wid & 7;      // 4 x 8 warp grid, warp tile 32x32
    const int g    = lane >> 2, tq = lane & 3;     // epilogue row/col mapping

    const __half* gA = g_xh + (size_t)(bm * BM) * D_DIM;
    const __half* gB = g_wh + (size_t)(bn * BN) * D_DIM;

    auto load_stage = [&](int bufi, int kc) {
        // B: 256 rows x 4 16B-chunks = 1024 cp.async (1/thread)
        {
            int row = tid >> 2, cg = tid & 3;
            const __half* srcB = gB + (size_t)row * D_DIM + kc * BK + cg * 8;
            uint32_t dstB = (uint32_t)__cvta_generic_to_shared(&sB[bufi * B_ELEMS + row * APITCH + cg * 8]);
            asm volatile("cp.async.cg.shared.global [%0], [%1], 16;\n" :: "r"(dstB), "l"(srcB) : "memory");
        }
        // A: 128 rows x 4 = 512 cp.async (threads 0..511)
        if (tid < 512) {
            int row = tid >> 2, cg = tid & 3;
            const __half* srcA = gA + (size_t)row * D_DIM + kc * BK + cg * 8;
            uint32_t dstA = (uint32_t)__cvta_generic_to_shared(&sA[bufi * A_ELEMS + row * APITCH + cg * 8]);
            asm volatile("cp.async.cg.shared.global [%0], [%1], 16;\n" :: "r"(dstA), "l"(srcA) : "memory");
        }
        asm volatile("cp.async.commit_group;\n" ::: "memory");
    };

    uint32_t acc[2][4][2];   // [mt][nt][f16x2 pair]
    #pragma unroll
    for (int a = 0; a < 2; a++)
        #pragma unroll
        for (int b2 = 0; b2 < 4; b2++) { acc[a][b2][0] = 0u; acc[a][b2][1] = 0u; }

    load_stage(0, 0);

    const int a_row = wm * 32 + ((lane >> 3) & 1) * 8 + (lane & 7);
    const int a_col = (lane >> 4) * 8;
    const int b_row = wn * 32 + (lane >> 4) * 8 + (lane & 7);
    const int b_col = ((lane >> 3) & 1) * 8;

    const uint32_t sa_base = (uint32_t)__cvta_generic_to_shared(sA);
    const uint32_t sb_base = (uint32_t)__cvta_generic_to_shared(sB);

    const int NKC = D_DIM / BK;   // 8
    for (int kc = 0; kc < NKC; kc++) {
        if (kc + 1 < NKC) {
            load_stage((kc + 1) & 1, kc + 1);
            asm volatile("cp.async.wait_group 1;\n" ::: "memory");
        } else {
            asm volatile("cp.async.wait_group 0;\n" ::: "memory");
        }
        __syncthreads();
        const int buf = kc & 1;
        const uint32_t sa = sa_base + buf * (A_ELEMS * 2);
        const uint32_t sb = sb_base + buf * (B_ELEMS * 2);

        #pragma unroll
        for (int ks = 0; ks < 2; ks++) {
            uint32_t a_frag[2][4];
            #pragma unroll
            for (int mt = 0; mt < 2; mt++) {
                uint32_t addr = sa + (uint32_t)(((a_row + mt * 16) * APITCH + ks * 16 + a_col) * 2);
                asm volatile("ldmatrix.sync.aligned.m8n8.x4.shared.b16 {%0,%1,%2,%3}, [%4];"
                             : "=r"(a_frag[mt][0]), "=r"(a_frag[mt][1]),
                               "=r"(a_frag[mt][2]), "=r"(a_frag[mt][3])
                             : "r"(addr));
            }
            uint32_t b_frag[4][2];
            #pragma unroll
            for (int np = 0; np < 2; np++) {
                uint32_t addr = sb + (uint32_t)(((b_row + np * 16) * APITCH + ks * 16 + b_col) * 2);
                uint32_t r0, r1, r2, r3;
                asm volatile("ldmatrix.sync.aligned.m8n8.x4.shared.b16 {%0,%1,%2,%3}, [%4];"
                             : "=r"(r0), "=r"(r1), "=r"(r2), "=r"(r3)
                             : "r"(addr));
                b_frag[np * 2][0]     = r0;  b_frag[np * 2][1]     = r1;
                b_frag[np * 2 + 1][0] = r2;  b_frag[np * 2 + 1][1] = r3;
            }
            #pragma unroll
            for (int mt = 0; mt < 2; mt++) {
                #pragma unroll
                for (int nt = 0; nt < 4; nt++) {
                    uint32_t* c = acc[mt][nt];
                    asm volatile(
                        "mma.sync.aligned.m16n8k16.row.col.f16.f16.f16.f16 "
                        "{%0,%1}, {%2,%3,%4,%5}, {%6,%7}, {%0,%1};\n"
                        : "+r"(c[0]), "+r"(c[1])
                        : "r"(a_frag[mt][0]), "r"(a_frag[mt][1]),
                          "r"(a_frag[mt][2]), "r"(a_frag[mt][3]),
                          "r"(b_frag[nt][0]), "r"(b_frag[nt][1]));
                }
            }
        }
        __syncthreads();
    }

    // epilogue: + b_enc, threshold-compact emit
    auto emit = [&](float v, int row, int col, float tau) {
        if (v > tau) {
            int p = atomicAdd(&g_cnt[row], 1);
            if (p < CAP)
                g_cand[(size_t)row * CAP + p] =
                    ((unsigned long long)__float_as_uint(v) << 32) | (unsigned)col;
        }
    };
    #pragma unroll
    for (int mt = 0; mt < 2; mt++) {
        const int r0 = bm * BM + wm * 32 + mt * 16 + g;
        const int r1 = r0 + 8;
        const float t0 = g_tau[r0], t1 = g_tau[r1];
        #pragma unroll
        for (int nt = 0; nt < 4; nt++) {
            const int col = bn * BN + wn * 32 + nt * 8 + tq * 2;
            const float be0 = b_enc[col], be1 = b_enc[col + 1];
            float2 lo = __half22float2(*(__half2*)&acc[mt][nt][0]);
            float2 hi = __half22float2(*(__half2*)&acc[mt][nt][1]);
            emit(lo.x + be0, r0, col,     t0);
            emit(lo.y + be1, r0, col + 1, t0);
            emit(hi.x + be0, r1, col,     t1);
            emit(hi.y + be1, r1, col + 1, t1);
        }
    }
}

// ---------------- K2: candidates -> top-64 -> exact recompute -> top-32 -> decode ----------------
#define SWP 36

__global__ void __launch_bounds__(256, 4) topk_decode_kernel(
    const float* __restrict__ x, const float* __restrict__ W_enc,
    const float* __restrict__ b_enc, const float* __restrict__ W_dec,
    const float* __restrict__ b_dec, float* __restrict__ out)
{
    __shared__ __align__(16) float sx[8][256];
    __shared__ __align__(16) float sw[8][32 * SWP];

    const int wid  = threadIdx.x >> 5;
    const int lane = threadIdx.x & 31;
    const int b    = blockIdx.x * 8 + wid;
    if (b >= B_TOK) return;

    {
        const float4* xp = (const float4*)(x + (size_t)b * D_DIM);
        #pragma unroll
        for (int q = 0; q < 2; q++) {
            float4 v = xp[lane + q * 32];
            float* d = &sx[wid][(lane + q * 32) * 4];
            d[0] = v.x; d[1] = v.y; d[2] = v.z; d[3] = v.w;
        }
        __syncwarp();
    }

    const int c = g_cnt[b];
    const bool bad = (c < K_TOP) || (c > CAP);

    float v0, v1; int i0, i1;
    bool valid1;

    auto chain8 = [&](float& accv, int ch) {
        const float4* wr = (const float4*)&sw[wid][lane * SWP];
        const float4* xc = (const float4*)&sx[wid][ch * 32];
        #pragma unroll
        for (int s = 0; s < 8; s++) {
            float4 wv = wr[s];
            float4 xv = xc[s];
            accv = fmaf(xv.x, wv.x, accv);
            accv = fmaf(xv.y, wv.y, accv);
            accv = fmaf(xv.z, wv.z, accv);
            accv = fmaf(xv.w, wv.w, accv);
        }
    };

    if (!bad) {
        {
            unsigned long long p0 = g_cand[(size_t)b * CAP + lane];
            v0 = __uint_as_float((unsigned)(p0 >> 32)); i0 = (int)(unsigned)p0;
        }
        valid1 = (32 + lane) < c;
        if (valid1) {
            unsigned long long p1 = g_cand[(size_t)b * CAP + 32 + lane];
            v1 = __uint_as_float((unsigned)(p1 >> 32)); i1 = (int)(unsigned)p1;
        } else { v1 = -1e30f; i1 = 0; }

        float thr = fminf(v0, v1);
        #pragma unroll
        for (int o = 16; o; o >>= 1) thr = fminf(thr, __shfl_xor_sync(0xffffffffu, thr, o));

        auto insert = [&](float cv, int ci) {
            float lmin; int lslot;
            if (v0 <= v1) { lmin = v0; lslot = 0; } else { lmin = v1; lslot = 1; }
            float mval = lmin; int mlan = lane;
            #pragma unroll
            for (int o = 16; o; o >>= 1) {
                float ov = __shfl_xor_sync(0xffffffffu, mval, o);
                int   ol = __shfl_xor_sync(0xffffffffu, mlan, o);
                if (ov < mval || (ov == mval && ol < mlan)) { mval = ov; mlan = ol; }
            }
            if (cv > mval && lane == mlan) {
                if (lslot == 0) { v0 = cv; i0 = ci; } else { v1 = cv; i1 = ci; }
            }
            thr = mval;
        };

        for (int base = 64; base < c; base += 32) {
            float cv = -1e30f; int ci = 0;
            if (base + lane < c) {
                unsigned long long pk = g_cand[(size_t)b * CAP + base + lane];
                cv = __uint_as_float((unsigned)(pk >> 32)); ci = (int)(unsigned)pk;
            }
            unsigned m = __ballot_sync(0xffffffffu, cv > thr);
            while (m) {
                int src = __ffs(m) - 1; m &= m - 1;
                float xv = __shfl_sync(0xffffffffu, cv, src);
                int   xi = __shfl_sync(0xffffffffu, ci, src);
                if (xv > thr) insert(xv, xi);
            }
        }
        valid1 = valid1 || (v1 > -1e29f);

        #pragma unroll
        for (int g2 = 0; g2 < 2; g2++) {
            const int myci = g2 ? i1 : i0;
            float accv = 0.0f;
            for (int ch = 0; ch < 8; ch++) {
                const int r = lane >> 3, cc = lane & 7;
                #pragma unroll
                for (int p = 0; p < 8; p++) {
                    int row  = p * 4 + r;
                    int crow = __shfl_sync(0xffffffffu, myci, row);
                    float4 v = *(const float4*)(W_enc + (size_t)crow * D_DIM + ch * 32 + cc * 4);
                    *(float4*)&sw[wid][row * SWP + cc * 4] = v;
                }
                __syncwarp();
                chain8(accv, ch);
                __syncwarp();
            }
            float d = fmaxf(accv + b_enc[myci], 0.0f);
            if (g2 == 0) v0 = d;
            else         v1 = valid1 ? d : -1e30f;
        }
    } else {
        float fv = -1e30f; int fi = 0; float thr32 = -1e30f;
        for (int stage = 0; stage < H_DIM / 32; stage++) {
            float accv = 0.0f;
            for (int ch = 0; ch < 8; ch++) {
                const int r = lane >> 3, cc = lane & 7;
                #pragma unroll
                for (int p = 0; p < 8; p++) {
                    int row  = p * 4 + r;
                    int crow = stage * 32 + row;
                    float4 v = *(const float4*)(W_enc + (size_t)crow * D_DIM + ch * 32 + cc * 4);
                    *(float4*)&sw[wid][row * SWP + cc * 4] = v;
                }
                __syncwarp();
                chain8(accv, ch);
                __syncwarp();
            }
            float d  = fmaxf(accv + b_enc[stage * 32 + lane], 0.0f);
            int   di = stage * 32 + lane;
            unsigned m = __ballot_sync(0xffffffffu, d > thr32);
            while (m) {
                int src = __ffs(m) - 1; m &= m - 1;
                float cv = __shfl_sync(0xffffffffu, d, src);
                int   ci = __shfl_sync(0xffffffffu, di, src);
                float mval = fv; int mlan = lane;
                #pragma unroll
                for (int o = 16; o; o >>= 1) {
                    float ov = __shfl_xor_sync(0xffffffffu, mval, o);
                    int   ol = __shfl_xor_sync(0xffffffffu, mlan, o);
                    if (ov < mval || (ov == mval && ol < mlan)) { mval = ov; mlan = ol; }
                }
                if (cv > mval && lane == mlan) { fv = cv; fi = ci; }
                thr32 = mval;
            }
        }
        v0 = fv; i0 = fi; v1 = -1e30f; i1 = 0;
    }

    float acc[8] = {0, 0, 0, 0, 0, 0, 0, 0};
    for (int t = 0; t < K_TOP; t++) {
        float mv; int ms, mi;
        if (v0 > v1 || (v0 == v1 && i0 <= i1)) { mv = v0; ms = 0; mi = i0; }
        else                                   { mv = v1; ms = 1; mi = i1; }
        int ml = lane;
        #pragma unroll
        for (int o = 16; o; o >>= 1) {
            float ov = __shfl_xor_sync(0xffffffffu, mv, o);
            int   oi = __shfl_xor_sync(0xffffffffu, mi, o);
            int   ol = __shfl_xor_sync(0xffffffffu, ml, o);
            int   os = __shfl_xor_sync(0xffffffffu, ms, o);
            if (ov > mv || (ov == mv && oi < mi)) { mv = ov; mi = oi; ml = ol; ms = os; }
        }
        if (lane == ml) { if (ms) v1 = -1e30f; else v0 = -1e30f; }

        const float4* dp = (const float4*)(W_dec + (size_t)mi * D_DIM + lane * 8);
        float4 d0 = dp[0], d1 = dp[1];
        acc[0] = fmaf(mv, d0.x, acc[0]); acc[1] = fmaf(mv, d0.y, acc[1]);
        acc[2] = fmaf(mv, d0.z, acc[2]); acc[3] = fmaf(mv, d0.w, acc[3]);
        acc[4] = fmaf(mv, d1.x, acc[4]); acc[5] = fmaf(mv, d1.y, acc[5]);
        acc[6] = fmaf(mv, d1.z, acc[6]); acc[7] = fmaf(mv, d1.w, acc[7]);
    }

    const float4* bdp = (const float4*)(b_dec + lane * 8);
    float4 bd0 = bdp[0], bd1 = bdp[1];
    float4* op = (float4*)(out + (size_t)b * D_DIM + lane * 8);
    op[0] = make_float4(acc[0] + bd0.x, acc[1] + bd0.y, acc[2] + bd0.z, acc[3] + bd0.w);
    op[1] = make_float4(acc[4] + bd1.x, acc[5] + bd1.y, acc[6] + bd1.z, acc[7] + bd1.w);
}

// ---------------- launch: simple sequential (overlap proven structurally dead) ----------------
static int s_attr = 0;

extern "C" void kernel_launch(void* const* d_in, const int* in_sizes, int n_in,
                              void* d_out, int out_size) {
    const float* x     = (const float*)d_in[0];
    const float* W_enc = (const float*)d_in[1];
    const float* b_enc = (const float*)d_in[2];
    const float* W_dec = (const float*)d_in[3];
    const float* b_dec = (const float*)d_in[4];
    float* out = (float*)d_out;

    if (!s_attr) {
        cudaFuncSetAttribute(enc_gemm_kernel,
                             cudaFuncAttributeMaxDynamicSharedMemorySize, GEMM_SMEM);
        s_attr = 1;
    }

    tau_kernel<<<B_TOK / 8, 256>>>(x);
    const long long nv = ((long long)B_TOK * D_DIM + (long long)H_DIM * D_DIM) / 4;
    cvt_kernel<<<(int)((nv + 255) / 256), 256>>>(x, W_enc);

    dim3 ggrid(H_DIM / BN, B_TOK / BM);   // (32, 256)
    enc_gemm_kernel<<<ggrid, 1024, GEMM_SMEM>>>(b_enc);

    topk_decode_kernel<<<B_TOK / 8, 256>>>(x, W_enc, b_enc, W_dec, b_dec, out);
}

// round 13
// speedup vs baseline: 1.1307x; 1.1307x over previous
#include <cuda_runtime.h>
#include <cuda_fp16.h>
#include <cstdint>

#define B_TOK 32768
#define D_DIM 256
#define H_DIM 8192
#define K_TOP 32
#define CAP   384

// ---------------- static scratch (no cudaMalloc allowed) ----------------
__device__ __align__(256) __half g_xh[(size_t)B_TOK * D_DIM];                // 16 MB
__device__ __align__(256) __half g_wh[(size_t)H_DIM * D_DIM];                //  4 MB
__device__ __align__(16) unsigned long long g_cand[(size_t)B_TOK * CAP];     // 100 MB
__device__ int   g_cnt[B_TOK];
__device__ float g_tau[B_TOK];

// ---------------- K01: per-token threshold + counter zero ----------------
__global__ void tau_kernel(const float* __restrict__ x) {
    const int wid  = threadIdx.x >> 5;
    const int lane = threadIdx.x & 31;
    const int b    = blockIdx.x * 8 + wid;
    if (b >= B_TOK) return;
    const float4* xp = (const float4*)(x + (size_t)b * D_DIM);
    float4 u0 = xp[lane], u1 = xp[lane + 32];
    float s = u0.x*u0.x + u0.y*u0.y + u0.z*u0.z + u0.w*u0.w
            + u1.x*u1.x + u1.y*u1.y + u1.z*u1.z + u1.w*u1.w;
    #pragma unroll
    for (int o = 16; o; o >>= 1) s += __shfl_xor_sync(0xffffffffu, s, o);
    if (lane == 0) {
        g_tau[b] = 0.0430f * sqrtf(s);   // 2.15 * 0.02 * ||x||
        g_cnt[b] = 0;
    }
}

// ---------------- K0: fp32 -> fp16 conversion ----------------
__global__ void cvt_kernel(const float* __restrict__ x, const float* __restrict__ w) {
    const long long n1 = (long long)B_TOK * D_DIM / 4;
    const long long n2 = (long long)H_DIM * D_DIM / 4;
    long long i = blockIdx.x * (long long)blockDim.x + threadIdx.x;
    if (i < n1) {
        float4 v = ((const float4*)x)[i];
        __half2* o = (__half2*)g_xh;
        o[2 * i]     = __floats2half2_rn(v.x, v.y);
        o[2 * i + 1] = __floats2half2_rn(v.z, v.w);
    } else if (i < n1 + n2) {
        long long j = i - n1;
        float4 v = ((const float4*)w)[j];
        __half2* o = (__half2*)g_wh;
        o[2 * j]     = __floats2half2_rn(v.x, v.y);
        o[2 * j + 1] = __floats2half2_rn(v.z, v.w);
    }
}

// ================= K1: fp16 HMMA GEMM (R10 config: 512 thr, 2 CTA/SM, tile 128x128) =================
#define BM 128
#define BN 128
#define BK 32
#define APITCH 40                       // f16 elems per smem row (32 + 8 pad); 80B rows
#define BUF_ELEMS (BM * APITCH)         // 5120 halfs = 10240 bytes per buffer

__global__ void __launch_bounds__(512, 2) enc_gemm_kernel(const float* __restrict__ b_enc) {
    __shared__ __align__(16) __half sA[2][BUF_ELEMS];
    __shared__ __align__(16) __half sB[2][BUF_ELEMS];

    const int tid  = threadIdx.x;
    const int bm   = blockIdx.y, bn = blockIdx.x;
    const int wid  = tid >> 5,  lane = tid & 31;
    const int wm   = wid >> 2,  wn = wid & 3;      // 4 x 4 warp grid, warp tile 32x32
    const int g    = lane >> 2, tq = lane & 3;     // epilogue row/col mapping

    const __half* gA = g_xh + (size_t)(bm * BM) * D_DIM;
    const __half* gB = g_wh + (size_t)(bn * BN) * D_DIM;

    auto load_stage = [&](int bufi, int kc) {
        int row = tid >> 2, cg = tid & 3;
        const __half* srcA = gA + (size_t)row * D_DIM + kc * BK + cg * 8;
        uint32_t dstA = (uint32_t)__cvta_generic_to_shared(&sA[bufi][row * APITCH + cg * 8]);
        asm volatile("cp.async.cg.shared.global [%0], [%1], 16;\n" :: "r"(dstA), "l"(srcA) : "memory");
        const __half* srcB = gB + (size_t)row * D_DIM + kc * BK + cg * 8;
        uint32_t dstB = (uint32_t)__cvta_generic_to_shared(&sB[bufi][row * APITCH + cg * 8]);
        asm volatile("cp.async.cg.shared.global [%0], [%1], 16;\n" :: "r"(dstB), "l"(srcB) : "memory");
        asm volatile("cp.async.commit_group;\n" ::: "memory");
    };

    uint32_t acc[2][4][2];   // [mt][nt][f16x2 pair]
    #pragma unroll
    for (int a = 0; a < 2; a++)
        #pragma unroll
        for (int b2 = 0; b2 < 4; b2++) { acc[a][b2][0] = 0u; acc[a][b2][1] = 0u; }

    load_stage(0, 0);

    const int a_row = wm * 32 + ((lane >> 3) & 1) * 8 + (lane & 7);
    const int a_col = (lane >> 4) * 8;
    const int b_row = wn * 32 + (lane >> 4) * 8 + (lane & 7);
    const int b_col = ((lane >> 3) & 1) * 8;

    const uint32_t sa_base = (uint32_t)__cvta_generic_to_shared(&sA[0][0]);
    const uint32_t sb_base = (uint32_t)__cvta_generic_to_shared(&sB[0][0]);
    const uint32_t buf_stride = BUF_ELEMS * 2;

    const int NKC = D_DIM / BK;   // 8
    for (int kc = 0; kc < NKC; kc++) {
        if (kc + 1 < NKC) {
            load_stage((kc + 1) & 1, kc + 1);
            asm volatile("cp.async.wait_group 1;\n" ::: "memory");
        } else {
            asm volatile("cp.async.wait_group 0;\n" ::: "memory");
        }
        __syncthreads();
        const int buf = kc & 1;
        const uint32_t sa = sa_base + buf * buf_stride;
        const uint32_t sb = sb_base + buf * buf_stride;

        #pragma unroll
        for (int ks = 0; ks < 2; ks++) {
            uint32_t a_frag[2][4];
            #pragma unroll
            for (int mt = 0; mt < 2; mt++) {
                uint32_t addr = sa + (uint32_t)(((a_row + mt * 16) * APITCH + ks * 16 + a_col) * 2);
                asm volatile("ldmatrix.sync.aligned.m8n8.x4.shared.b16 {%0,%1,%2,%3}, [%4];"
                             : "=r"(a_frag[mt][0]), "=r"(a_frag[mt][1]),
                               "=r"(a_frag[mt][2]), "=r"(a_frag[mt][3])
                             : "r"(addr));
            }
            uint32_t b_frag[4][2];
            #pragma unroll
            for (int np = 0; np < 2; np++) {
                uint32_t addr = sb + (uint32_t)(((b_row + np * 16) * APITCH + ks * 16 + b_col) * 2);
                uint32_t r0, r1, r2, r3;
                asm volatile("ldmatrix.sync.aligned.m8n8.x4.shared.b16 {%0,%1,%2,%3}, [%4];"
                             : "=r"(r0), "=r"(r1), "=r"(r2), "=r"(r3)
                             : "r"(addr));
                b_frag[np * 2][0]     = r0;  b_frag[np * 2][1]     = r1;
                b_frag[np * 2 + 1][0] = r2;  b_frag[np * 2 + 1][1] = r3;
            }
            #pragma unroll
            for (int mt = 0; mt < 2; mt++) {
                #pragma unroll
                for (int nt = 0; nt < 4; nt++) {
                    uint32_t* c = acc[mt][nt];
                    asm volatile(
                        "mma.sync.aligned.m16n8k16.row.col.f16.f16.f16.f16 "
                        "{%0,%1}, {%2,%3,%4,%5}, {%6,%7}, {%0,%1};\n"
                        : "+r"(c[0]), "+r"(c[1])
                        : "r"(a_frag[mt][0]), "r"(a_frag[mt][1]),
                          "r"(a_frag[mt][2]), "r"(a_frag[mt][3]),
                          "r"(b_frag[nt][0]), "r"(b_frag[nt][1]));
                }
            }
        }
        __syncthreads();
    }

    // epilogue: + b_enc, threshold-compact emit
    auto emit = [&](float v, int row, int col, float tau) {
        if (v > tau) {
            int p = atomicAdd(&g_cnt[row], 1);
            if (p < CAP)
                g_cand[(size_t)row * CAP + p] =
                    ((unsigned long long)__float_as_uint(v) << 32) | (unsigned)col;
        }
    };
    #pragma unroll
    for (int mt = 0; mt < 2; mt++) {
        const int r0 = bm * BM + wm * 32 + mt * 16 + g;
        const int r1 = r0 + 8;
        const float t0 = g_tau[r0], t1 = g_tau[r1];
        #pragma unroll
        for (int nt = 0; nt < 4; nt++) {
            const int col = bn * BN + wn * 32 + nt * 8 + tq * 2;
            const float be0 = b_enc[col], be1 = b_enc[col + 1];
            float2 lo = __half22float2(*(__half2*)&acc[mt][nt][0]);
            float2 hi = __half22float2(*(__half2*)&acc[mt][nt][1]);
            emit(lo.x + be0, r0, col,     t0);
            emit(lo.y + be1, r0, col + 1, t0);
            emit(hi.x + be0, r1, col,     t1);
            emit(hi.y + be1, r1, col + 1, t1);
        }
    }
}

// ---------------- K2: candidates -> top-64 -> exact recompute -> keyed top-32 -> decode ----------------
#define SWP 36

// order-preserving float->u32 (valid for all floats; for v>=0 it's bits|0x80000000)
__device__ __forceinline__ unsigned fkey(float f) {
    unsigned b = __float_as_uint(f);
    return b ^ ((b & 0x80000000u) ? 0xffffffffu : 0x80000000u);
}

__global__ void __launch_bounds__(256, 4) topk_decode_kernel(
    const float* __restrict__ x, const float* __restrict__ W_enc,
    const float* __restrict__ b_enc, const float* __restrict__ W_dec,
    const float* __restrict__ b_dec, float* __restrict__ out)
{
    __shared__ __align__(16) float sx[8][256];
    __shared__ __align__(16) float sw[8][32 * SWP];

    const int wid  = threadIdx.x >> 5;
    const int lane = threadIdx.x & 31;
    const int b    = blockIdx.x * 8 + wid;
    if (b >= B_TOK) return;

    {
        const float4* xp = (const float4*)(x + (size_t)b * D_DIM);
        #pragma unroll
        for (int q = 0; q < 2; q++) {
            float4 v = xp[lane + q * 32];
            float* d = &sx[wid][(lane + q * 32) * 4];
            d[0] = v.x; d[1] = v.y; d[2] = v.z; d[3] = v.w;
        }
        __syncwarp();
    }

    const int c = g_cnt[b];
    const bool bad = (c < K_TOP) || (c > CAP);

    float v0, v1; int i0, i1;
    bool valid1 = false;

    auto chain8 = [&](float& accv, int ch) {
        const float4* wr = (const float4*)&sw[wid][lane * SWP];
        const float4* xc = (const float4*)&sx[wid][ch * 32];
        #pragma unroll
        for (int s = 0; s < 8; s++) {
            float4 wv = wr[s];
            float4 xv = xc[s];
            accv = fmaf(xv.x, wv.x, accv);
            accv = fmaf(xv.y, wv.y, accv);
            accv = fmaf(xv.z, wv.z, accv);
            accv = fmaf(xv.w, wv.w, accv);
        }
    };

    unsigned long long k0, k1;   // packed (orderable value | ~idx) keys for extraction

    if (!bad) {
        {
            unsigned long long p0 = g_cand[(size_t)b * CAP + lane];
            v0 = __uint_as_float((unsigned)(p0 >> 32)); i0 = (int)(unsigned)p0;
        }
        valid1 = (32 + lane) < c;
        if (valid1) {
            unsigned long long p1 = g_cand[(size_t)b * CAP + 32 + lane];
            v1 = __uint_as_float((unsigned)(p1 >> 32)); i1 = (int)(unsigned)p1;
        } else { v1 = -1e30f; i1 = 0; }

        float thr = fminf(v0, v1);
        #pragma unroll
        for (int o = 16; o; o >>= 1) thr = fminf(thr, __shfl_xor_sync(0xffffffffu, thr, o));

        auto insert = [&](float cv, int ci) {
            float lmin; int lslot;
            if (v0 <= v1) { lmin = v0; lslot = 0; } else { lmin = v1; lslot = 1; }
            float mval = lmin; int mlan = lane;
            #pragma unroll
            for (int o = 16; o; o >>= 1) {
                float ov = __shfl_xor_sync(0xffffffffu, mval, o);
                int   ol = __shfl_xor_sync(0xffffffffu, mlan, o);
                if (ov < mval || (ov == mval && ol < mlan)) { mval = ov; mlan = ol; }
            }
            if (cv > mval && lane == mlan) {
                if (lslot == 0) { v0 = cv; i0 = ci; } else { v1 = cv; i1 = ci; }
            }
            thr = mval;
        };

        for (int base = 64; base < c; base += 32) {
            float cv = -1e30f; int ci = 0;
            if (base + lane < c) {
                unsigned long long pk = g_cand[(size_t)b * CAP + base + lane];
                cv = __uint_as_float((unsigned)(pk >> 32)); ci = (int)(unsigned)pk;
            }
            unsigned m = __ballot_sync(0xffffffffu, cv > thr);
            while (m) {
                int src = __ffs(m) - 1; m &= m - 1;
                float xv = __shfl_sync(0xffffffffu, cv, src);
                int   xi = __shfl_sync(0xffffffffu, ci, src);
                if (xv > thr) insert(xv, xi);
            }
        }
        valid1 = valid1 || (v1 > -1e29f);

        // exact recompute (cublas chain order) for the 64 slots
        #pragma unroll
        for (int g2 = 0; g2 < 2; g2++) {
            const int myci = g2 ? i1 : i0;
            float accv = 0.0f;
            for (int ch = 0; ch < 8; ch++) {
                const int r = lane >> 3, cc = lane & 7;
                #pragma unroll
                for (int p = 0; p < 8; p++) {
                    int row  = p * 4 + r;
                    int crow = __shfl_sync(0xffffffffu, myci, row);
                    float4 v = *(const float4*)(W_enc + (size_t)crow * D_DIM + ch * 32 + cc * 4);
                    *(float4*)&sw[wid][row * SWP + cc * 4] = v;
                }
                __syncwarp();
                chain8(accv, ch);
                __syncwarp();
            }
            float d = fmaxf(accv + b_enc[myci], 0.0f);
            if (g2 == 0) v0 = d;
            else         v1 = d;
        }
        k0 = ((unsigned long long)fkey(v0) << 32) | (unsigned)(~(unsigned)i0);
        k1 = valid1 ? (((unsigned long long)fkey(v1) << 32) | (unsigned)(~(unsigned)i1)) : 0ull;
    } else {
        // fallback: exact brute force over all H (never expected)
        float fv = -1e30f; int fi = 0; float thr32 = -1e30f;
        for (int stage = 0; stage < H_DIM / 32; stage++) {
            float accv = 0.0f;
            for (int ch = 0; ch < 8; ch++) {
                const int r = lane >> 3, cc = lane & 7;
                #pragma unroll
                for (int p = 0; p < 8; p++) {
                    int row  = p * 4 + r;
                    int crow = stage * 32 + row;
                    float4 v = *(const float4*)(W_enc + (size_t)crow * D_DIM + ch * 32 + cc * 4);
                    *(float4*)&sw[wid][row * SWP + cc * 4] = v;
                }
                __syncwarp();
                chain8(accv, ch);
                __syncwarp();
            }
            float d  = fmaxf(accv + b_enc[stage * 32 + lane], 0.0f);
            int   di = stage * 32 + lane;
            unsigned m = __ballot_sync(0xffffffffu, d > thr32);
            while (m) {
                int src = __ffs(m) - 1; m &= m - 1;
                float cv = __shfl_sync(0xffffffffu, d, src);
                int   ci = __shfl_sync(0xffffffffu, di, src);
                float mval = fv; int mlan = lane;
                #pragma unroll
                for (int o = 16; o; o >>= 1) {
                    float ov = __shfl_xor_sync(0xffffffffu, mval, o);
                    int   ol = __shfl_xor_sync(0xffffffffu, mlan, o);
                    if (ov < mval || (ov == mval && ol < mlan)) { mval = ov; mlan = ol; }
                }
                if (cv > mval && lane == mlan) { fv = cv; fi = ci; }
                thr32 = mval;
            }
        }
        k0 = ((unsigned long long)fkey(fv) << 32) | (unsigned)(~(unsigned)fi);
        k1 = 0ull;
    }

    // keyed top-32 extraction (desc value, asc index) fused with decode (exact fmaf chain order)
    float acc[8] = {0, 0, 0, 0, 0, 0, 0, 0};
    for (int t = 0; t < K_TOP; t++) {
        unsigned long long m = (k0 > k1) ? k0 : k1;
        #pragma unroll
        for (int o = 16; o; o >>= 1) {
            unsigned long long om = __shfl_xor_sync(0xffffffffu, m, o);
            if (om > m) m = om;
        }
        const int   idx = (int)(~(unsigned)(m & 0xffffffffu));
        const unsigned vb = (unsigned)(m >> 32);
        const float mv = __uint_as_float(vb ^ ((vb & 0x80000000u) ? 0x80000000u : 0xffffffffu));
        if (k0 == m)      k0 = 0ull;
        else if (k1 == m) k1 = 0ull;

        const float4* dp = (const float4*)(W_dec + (size_t)idx * D_DIM + lane * 8);
        float4 d0 = dp[0], d1 = dp[1];
        acc[0] = fmaf(mv, d0.x, acc[0]); acc[1] = fmaf(mv, d0.y, acc[1]);
        acc[2] = fmaf(mv, d0.z, acc[2]); acc[3] = fmaf(mv, d0.w, acc[3]);
        acc[4] = fmaf(mv, d1.x, acc[4]); acc[5] = fmaf(mv, d1.y, acc[5]);
        acc[6] = fmaf(mv, d1.z, acc[6]); acc[7] = fmaf(mv, d1.w, acc[7]);
    }

    const float4* bdp = (const float4*)(b_dec + lane * 8);
    float4 bd0 = bdp[0], bd1 = bdp[1];
    float4* op = (float4*)(out + (size_t)b * D_DIM + lane * 8);
    op[0] = make_float4(acc[0] + bd0.x, acc[1] + bd0.y, acc[2] + bd0.z, acc[3] + bd0.w);
    op[1] = make_float4(acc[4] + bd1.x, acc[5] + bd1.y, acc[6] + bd1.z, acc[7] + bd1.w);
}

// ---------------- launch ----------------
extern "C" void kernel_launch(void* const* d_in, const int* in_sizes, int n_in,
                              void* d_out, int out_size) {
    const float* x     = (const float*)d_in[0];
    const float* W_enc = (const float*)d_in[1];
    const float* b_enc = (const float*)d_in[2];
    const float* W_dec = (const float*)d_in[3];
    const float* b_dec = (const float*)d_in[4];
    float* out = (float*)d_out;

    tau_kernel<<<B_TOK / 8, 256>>>(x);
    const long long nv = ((long long)B_TOK * D_DIM + (long long)H_DIM * D_DIM) / 4;
    cvt_kernel<<<(int)((nv + 255) / 256), 256>>>(x, W_enc);

    dim3 ggrid(H_DIM / BN, B_TOK / BM);   // (64, 256)
    enc_gemm_kernel<<<ggrid, 512>>>(b_enc);

    topk_decode_kernel<<<B_TOK / 8, 256>>>(x, W_enc, b_enc, W_dec, b_dec, out);
}

// round 15
// speedup vs baseline: 1.2512x; 1.1066x over previous
#include <cuda_runtime.h>
#include <cuda_fp16.h>
#include <cstdint>

#define B_TOK 32768
#define D_DIM 256
#define H_DIM 8192
#define K_TOP 32
#define CAP   384

// ---------------- static scratch (no cudaMalloc allowed) ----------------
__device__ __align__(256) __half g_xh[(size_t)B_TOK * D_DIM];                // 16 MB
__device__ __align__(256) __half g_wh[(size_t)H_DIM * D_DIM];                //  4 MB
__device__ __align__(16) unsigned long long g_cand[(size_t)B_TOK * CAP];     // 100 MB
__device__ int   g_cnt[B_TOK];
__device__ float g_tau[B_TOK];

// ---------------- K01: per-token threshold + counter zero ----------------
__global__ void tau_kernel(const float* __restrict__ x) {
    const int wid  = threadIdx.x >> 5;
    const int lane = threadIdx.x & 31;
    const int b    = blockIdx.x * 8 + wid;
    if (b >= B_TOK) return;
    const float4* xp = (const float4*)(x + (size_t)b * D_DIM);
    float4 u0 = xp[lane], u1 = xp[lane + 32];
    float s = u0.x*u0.x + u0.y*u0.y + u0.z*u0.z + u0.w*u0.w
            + u1.x*u1.x + u1.y*u1.y + u1.z*u1.z + u1.w*u1.w;
    #pragma unroll
    for (int o = 16; o; o >>= 1) s += __shfl_xor_sync(0xffffffffu, s, o);
    if (lane == 0) {
        g_tau[b] = 0.0450f * sqrtf(s);   // 2.25 * 0.02 * ||x||
        g_cnt[b] = 0;
    }
}

// ---------------- K0: fp32 -> fp16 conversion ----------------
__global__ void cvt_kernel(const float* __restrict__ x, const float* __restrict__ w) {
    const long long n1 = (long long)B_TOK * D_DIM / 4;
    const long long n2 = (long long)H_DIM * D_DIM / 4;
    long long i = blockIdx.x * (long long)blockDim.x + threadIdx.x;
    if (i < n1) {
        float4 v = ((const float4*)x)[i];
        __half2* o = (__half2*)g_xh;
        o[2 * i]     = __floats2half2_rn(v.x, v.y);
        o[2 * i + 1] = __floats2half2_rn(v.z, v.w);
    } else if (i < n1 + n2) {
        long long j = i - n1;
        float4 v = ((const float4*)w)[j];
        __half2* o = (__half2*)g_wh;
        o[2 * j]     = __floats2half2_rn(v.x, v.y);
        o[2 * j + 1] = __floats2half2_rn(v.z, v.w);
    }
}

// ================= K1: fp16 HMMA GEMM (R12 config: 512 thr, 2 CTA/SM, tile 128x128, f16 acc) =================
#define BM 128
#define BN 128
#define BK 32
#define APITCH 40                       // f16 elems per smem row (32 + 8 pad); 80B rows
#define BUF_ELEMS (BM * APITCH)         // 5120 halfs = 10240 bytes per buffer

__global__ void __launch_bounds__(512, 2) enc_gemm_kernel(const float* __restrict__ b_enc) {
    __shared__ __align__(16) __half sA[2][BUF_ELEMS];
    __shared__ __align__(16) __half sB[2][BUF_ELEMS];

    const int tid  = threadIdx.x;
    const int bm   = blockIdx.y, bn = blockIdx.x;
    const int wid  = tid >> 5,  lane = tid & 31;
    const int wm   = wid >> 2,  wn = wid & 3;      // 4 x 4 warp grid, warp tile 32x32
    const int g    = lane >> 2, tq = lane & 3;     // epilogue row/col mapping

    const __half* gA = g_xh + (size_t)(bm * BM) * D_DIM;
    const __half* gB = g_wh + (size_t)(bn * BN) * D_DIM;

    auto load_stage = [&](int bufi, int kc) {
        int row = tid >> 2, cg = tid & 3;
        const __half* srcA = gA + (size_t)row * D_DIM + kc * BK + cg * 8;
        uint32_t dstA = (uint32_t)__cvta_generic_to_shared(&sA[bufi][row * APITCH + cg * 8]);
        asm volatile("cp.async.cg.shared.global [%0], [%1], 16;\n" :: "r"(dstA), "l"(srcA) : "memory");
        const __half* srcB = gB + (size_t)row * D_DIM + kc * BK + cg * 8;
        uint32_t dstB = (uint32_t)__cvta_generic_to_shared(&sB[bufi][row * APITCH + cg * 8]);
        asm volatile("cp.async.cg.shared.global [%0], [%1], 16;\n" :: "r"(dstB), "l"(srcB) : "memory");
        asm volatile("cp.async.commit_group;\n" ::: "memory");
    };

    uint32_t acc[2][4][2];   // f16x2 accumulators
    #pragma unroll
    for (int a = 0; a < 2; a++)
        #pragma unroll
        for (int b2 = 0; b2 < 4; b2++) { acc[a][b2][0] = 0u; acc[a][b2][1] = 0u; }

    load_stage(0, 0);

    const int a_row = wm * 32 + ((lane >> 3) & 1) * 8 + (lane & 7);
    const int a_col = (lane >> 4) * 8;
    const int b_row = wn * 32 + (lane >> 4) * 8 + (lane & 7);
    const int b_col = ((lane >> 3) & 1) * 8;

    const uint32_t sa_base = (uint32_t)__cvta_generic_to_shared(&sA[0][0]);
    const uint32_t sb_base = (uint32_t)__cvta_generic_to_shared(&sB[0][0]);
    const uint32_t buf_stride = BUF_ELEMS * 2;

    const int NKC = D_DIM / BK;   // 8
    for (int kc = 0; kc < NKC; kc++) {
        if (kc + 1 < NKC) {
            load_stage((kc + 1) & 1, kc + 1);
            asm volatile("cp.async.wait_group 1;\n" ::: "memory");
        } else {
            asm volatile("cp.async.wait_group 0;\n" ::: "memory");
        }
        __syncthreads();
        const int buf = kc & 1;
        const uint32_t sa = sa_base + buf * buf_stride;
        const uint32_t sb = sb_base + buf * buf_stride;

        #pragma unroll
        for (int ks = 0; ks < 2; ks++) {
            uint32_t a_frag[2][4];
            #pragma unroll
            for (int mt = 0; mt < 2; mt++) {
                uint32_t addr = sa + (uint32_t)(((a_row + mt * 16) * APITCH + ks * 16 + a_col) * 2);
                asm volatile("ldmatrix.sync.aligned.m8n8.x4.shared.b16 {%0,%1,%2,%3}, [%4];"
                             : "=r"(a_frag[mt][0]), "=r"(a_frag[mt][1]),
                               "=r"(a_frag[mt][2]), "=r"(a_frag[mt][3])
                             : "r"(addr));
            }
            uint32_t b_frag[4][2];
            #pragma unroll
            for (int np = 0; np < 2; np++) {
                uint32_t addr = sb + (uint32_t)(((b_row + np * 16) * APITCH + ks * 16 + b_col) * 2);
                uint32_t r0, r1, r2, r3;
                asm volatile("ldmatrix.sync.aligned.m8n8.x4.shared.b16 {%0,%1,%2,%3}, [%4];"
                             : "=r"(r0), "=r"(r1), "=r"(r2), "=r"(r3)
                             : "r"(addr));
                b_frag[np * 2][0]     = r0;  b_frag[np * 2][1]     = r1;
                b_frag[np * 2 + 1][0] = r2;  b_frag[np * 2 + 1][1] = r3;
            }
            #pragma unroll
            for (int mt = 0; mt < 2; mt++) {
                #pragma unroll
                for (int nt = 0; nt < 4; nt++) {
                    uint32_t* c = acc[mt][nt];
                    asm volatile(
                        "mma.sync.aligned.m16n8k16.row.col.f16.f16.f16.f16 "
                        "{%0,%1}, {%2,%3,%4,%5}, {%6,%7}, {%0,%1};\n"
                        : "+r"(c[0]), "+r"(c[1])
                        : "r"(a_frag[mt][0]), "r"(a_frag[mt][1]),
                          "r"(a_frag[mt][2]), "r"(a_frag[mt][3]),
                          "r"(b_frag[nt][0]), "r"(b_frag[nt][1]));
                }
            }
        }
        __syncthreads();
    }

    // epilogue: + b_enc, threshold-compact emit
    auto emit = [&](float v, int row, int col, float tau) {
        if (v > tau) {
            int p = atomicAdd(&g_cnt[row], 1);
            if (p < CAP)
                g_cand[(size_t)row * CAP + p] =
                    ((unsigned long long)__float_as_uint(v) << 32) | (unsigned)col;
        }
    };
    #pragma unroll
    for (int mt = 0; mt < 2; mt++) {
        const int r0 = bm * BM + wm * 32 + mt * 16 + g;
        const int r1 = r0 + 8;
        const float t0 = g_tau[r0], t1 = g_tau[r1];
        #pragma unroll
        for (int nt = 0; nt < 4; nt++) {
            const int col = bn * BN + wn * 32 + nt * 8 + tq * 2;
            const float be0 = b_enc[col], be1 = b_enc[col + 1];
            float2 lo = __half22float2(*(__half2*)&acc[mt][nt][0]);
            float2 hi = __half22float2(*(__half2*)&acc[mt][nt][1]);
            emit(lo.x + be0, r0, col,     t0);
            emit(lo.y + be1, r0, col + 1, t0);
            emit(hi.x + be0, r1, col,     t1);
            emit(hi.y + be1, r1, col + 1, t1);
        }
    }
}

// ---------------- K2: candidates -> top-64 -> exact recompute (conflict-free smem) -> keyed top-32 -> decode ----------------
#define SWP 34   // floats per staged row: (34*lane) mod 32 == 2*lane -> conflict-free float2 within half-warp phases

__device__ __forceinline__ unsigned fkey(float f) {
    unsigned b = __float_as_uint(f);
    return b ^ ((b & 0x80000000u) ? 0xffffffffu : 0x80000000u);
}

__global__ void __launch_bounds__(256, 4) topk_decode_kernel(
    const float* __restrict__ x, const float* __restrict__ W_enc,
    const float* __restrict__ b_enc, const float* __restrict__ W_dec,
    const float* __restrict__ b_dec, float* __restrict__ out)
{
    __shared__ __align__(16) float sx[8][256];
    __shared__ __align__(8) float sw[8][32 * SWP];

    const int wid  = threadIdx.x >> 5;
    const int lane = threadIdx.x & 31;
    const int b    = blockIdx.x * 8 + wid;
    if (b >= B_TOK) return;

    {
        const float4* xp = (const float4*)(x + (size_t)b * D_DIM);
        #pragma unroll
        for (int q = 0; q < 2; q++) {
            float4 v = xp[lane + q * 32];
            float* d = &sx[wid][(lane + q * 32) * 4];
            d[0] = v.x; d[1] = v.y; d[2] = v.z; d[3] = v.w;
        }
        __syncwarp();
    }

    const int c = g_cnt[b];
    const bool bad = (c < K_TOP) || (c > CAP);

    float v0, v1; int i0, i1;
    bool valid1 = false;

    // strict ascending-k single-accumulator chain over one 32-float chunk (bit-exact order)
    auto chain8 = [&](float& accv, int ch) {
        const float2* wr = (const float2*)&sw[wid][lane * SWP];
        const float4* xc = (const float4*)&sx[wid][ch * 32];
        #pragma unroll
        for (int s = 0; s < 8; s++) {
            float4 xv = xc[s];
            float2 w0 = wr[s * 2];
            float2 w1 = wr[s * 2 + 1];
            accv = fmaf(xv.x, w0.x, accv);
            accv = fmaf(xv.y, w0.y, accv);
            accv = fmaf(xv.z, w1.x, accv);
            accv = fmaf(xv.w, w1.y, accv);
        }
    };
    // conflict-free staging: coalesced float4 LDG, split into two float2 STS
    auto stage_rows = [&](int myci, int ch, bool broadcast_stage, int stage_base) {
        const int r = lane >> 3, cc = lane & 7;
        #pragma unroll
        for (int p = 0; p < 8; p++) {
            int row  = p * 4 + r;
            int crow = broadcast_stage ? (stage_base + row) : __shfl_sync(0xffffffffu, myci, row);
            float4 v = *(const float4*)(W_enc + (size_t)crow * D_DIM + ch * 32 + cc * 4);
            float* dst = &sw[wid][row * SWP + cc * 4];
            *(float2*)(dst)     = make_float2(v.x, v.y);
            *(float2*)(dst + 2) = make_float2(v.z, v.w);
        }
        __syncwarp();
    };

    unsigned long long k0, k1;

    if (!bad) {
        {
            unsigned long long p0 = g_cand[(size_t)b * CAP + lane];
            v0 = __uint_as_float((unsigned)(p0 >> 32)); i0 = (int)(unsigned)p0;
        }
        valid1 = (32 + lane) < c;
        if (valid1) {
            unsigned long long p1 = g_cand[(size_t)b * CAP + 32 + lane];
            v1 = __uint_as_float((unsigned)(p1 >> 32)); i1 = (int)(unsigned)p1;
        } else { v1 = -1e30f; i1 = 0; }

        float thr = fminf(v0, v1);
        #pragma unroll
        for (int o = 16; o; o >>= 1) thr = fminf(thr, __shfl_xor_sync(0xffffffffu, thr, o));

        auto insert = [&](float cv, int ci) {
            float lmin; int lslot;
            if (v0 <= v1) { lmin = v0; lslot = 0; } else { lmin = v1; lslot = 1; }
            float mval = lmin; int mlan = lane;
            #pragma unroll
            for (int o = 16; o; o >>= 1) {
                float ov = __shfl_xor_sync(0xffffffffu, mval, o);
                int   ol = __shfl_xor_sync(0xffffffffu, mlan, o);
                if (ov < mval || (ov == mval && ol < mlan)) { mval = ov; mlan = ol; }
            }
            if (cv > mval && lane == mlan) {
                if (lslot == 0) { v0 = cv; i0 = ci; } else { v1 = cv; i1 = ci; }
            }
            thr = mval;
        };

        for (int base = 64; base < c; base += 32) {
            float cv = -1e30f; int ci = 0;
            if (base + lane < c) {
                unsigned long long pk = g_cand[(size_t)b * CAP + base + lane];
                cv = __uint_as_float((unsigned)(pk >> 32)); ci = (int)(unsigned)pk;
            }
            unsigned m = __ballot_sync(0xffffffffu, cv > thr);
            while (m) {
                int src = __ffs(m) - 1; m &= m - 1;
                float xv = __shfl_sync(0xffffffffu, cv, src);
                int   xi = __shfl_sync(0xffffffffu, ci, src);
                if (xv > thr) insert(xv, xi);
            }
        }
        valid1 = valid1 || (v1 > -1e29f);

        // exact recompute (cublas chain order) for the 64 slots
        #pragma unroll
        for (int g2 = 0; g2 < 2; g2++) {
            const int myci = g2 ? i1 : i0;
            float accv = 0.0f;
            for (int ch = 0; ch < 8; ch++) {
                stage_rows(myci, ch, false, 0);
                chain8(accv, ch);
                __syncwarp();
            }
            float d = fmaxf(accv + b_enc[myci], 0.0f);
            if (g2 == 0) v0 = d;
            else         v1 = d;
        }
        k0 = ((unsigned long long)fkey(v0) << 32) | (unsigned)(~(unsigned)i0);
        k1 = valid1 ? (((unsigned long long)fkey(v1) << 32) | (unsigned)(~(unsigned)i1)) : 0ull;
    } else {
        // fallback: exact brute force over all H (never expected)
        float fv = -1e30f; int fi = 0; float thr32 = -1e30f;
        for (int stage = 0; stage < H_DIM / 32; stage++) {
            float accv = 0.0f;
            for (int ch = 0; ch < 8; ch++) {
                stage_rows(0, ch, true, stage * 32);
                chain8(accv, ch);
                __syncwarp();
            }
            float d  = fmaxf(accv + b_enc[stage * 32 + lane], 0.0f);
            int   di = stage * 32 + lane;
            unsigned m = __ballot_sync(0xffffffffu, d > thr32);
            while (m) {
                int src = __ffs(m) - 1; m &= m - 1;
                float cv = __shfl_sync(0xffffffffu, d, src);
                int   ci = __shfl_sync(0xffffffffu, di, src);
                float mval = fv; int mlan = lane;
                #pragma unroll
                for (int o = 16; o; o >>= 1) {
                    float ov = __shfl_xor_sync(0xffffffffu, mval, o);
                    int   ol = __shfl_xor_sync(0xffffffffu, mlan, o);
                    if (ov < mval || (ov == mval && ol < mlan)) { mval = ov; mlan = ol; }
                }
                if (cv > mval && lane == mlan) { fv = cv; fi = ci; }
                thr32 = mval;
            }
        }
        k0 = ((unsigned long long)fkey(fv) << 32) | (unsigned)(~(unsigned)fi);
        k1 = 0ull;
    }

    // keyed top-32 extraction (desc value, asc index) fused with decode (exact fmaf chain order)
    float acc[8] = {0, 0, 0, 0, 0, 0, 0, 0};
    for (int t = 0; t < K_TOP; t++) {
        unsigned long long m = (k0 > k1) ? k0 : k1;
        #pragma unroll
        for (int o = 16; o; o >>= 1) {
            unsigned long long om = __shfl_xor_sync(0xffffffffu, m, o);
            if (om > m) m = om;
        }
        const int   idx = (int)(~(unsigned)(m & 0xffffffffu));
        const unsigned vb = (unsigned)(m >> 32);
        const float mv = __uint_as_float(vb ^ ((vb & 0x80000000u) ? 0x80000000u : 0xffffffffu));
        if (k0 == m)      k0 = 0ull;
        else if (k1 == m) k1 = 0ull;

        const float4* dp = (const float4*)(W_dec + (size_t)idx * D_DIM + lane * 8);
        float4 d0 = dp[0], d1 = dp[1];
        acc[0] = fmaf(mv, d0.x, acc[0]); acc[1] = fmaf(mv, d0.y, acc[1]);
        acc[2] = fmaf(mv, d0.z, acc[2]); acc[3] = fmaf(mv, d0.w, acc[3]);
        acc[4] = fmaf(mv, d1.x, acc[4]); acc[5] = fmaf(mv, d1.y, acc[5]);
        acc[6] = fmaf(mv, d1.z, acc[6]); acc[7] = fmaf(mv, d1.w, acc[7]);
    }

    const float4* bdp = (const float4*)(b_dec + lane * 8);
    float4 bd0 = bdp[0], bd1 = bdp[1];
    float4* op = (float4*)(out + (size_t)b * D_DIM + lane * 8);
    op[0] = make_float4(acc[0] + bd0.x, acc[1] + bd0.y, acc[2] + bd0.z, acc[3] + bd0.w);
    op[1] = make_float4(acc[4] + bd1.x, acc[5] + bd1.y, acc[6] + bd1.z, acc[7] + bd1.w);
}

// ---------------- launch ----------------
extern "C" void kernel_launch(void* const* d_in, const int* in_sizes, int n_in,
                              void* d_out, int out_size) {
    const float* x     = (const float*)d_in[0];
    const float* W_enc = (const float*)d_in[1];
    const float* b_enc = (const float*)d_in[2];
    const float* W_dec = (const float*)d_in[3];
    const float* b_dec = (const float*)d_in[4];
    float* out = (float*)d_out;

    tau_kernel<<<B_TOK / 8, 256>>>(x);
    const long long nv = ((long long)B_TOK * D_DIM + (long long)H_DIM * D_DIM) / 4;
    cvt_kernel<<<(int)((nv + 255) / 256), 256>>>(x, W_enc);

    dim3 ggrid(H_DIM / BN, B_TOK / BM);   // (64, 256)
    enc_gemm_kernel<<<ggrid, 512>>>(b_enc);

    topk_decode_kernel<<<B_TOK / 8, 256>>>(x, W_enc, b_enc, W_dec, b_dec, out);
}